// round 3
// baseline (speedup 1.0000x reference)
#include <cuda_runtime.h>
#include <cuda_bf16.h>
#include <math.h>

// Problem constants
#define B_      4096
#define STOCH_  1024
#define ACT_    32
#define DETER_  4096
#define T_      16
#define D_      256
#define S_      256
#define L_      4
#define KIN_    (STOCH_ + ACT_)   // 1056
#define EPS_    1e-4f
#define M_BIG   (B_ * T_)         // 65536

// ---------------- scratch (device globals; no allocation) ----------------
__device__ float g_tokA[M_BIG * D_];      // token buffer A
__device__ float g_tokB[M_BIG * D_];      // token buffer B (ping-pong)
__device__ float g_states[M_BIG * S_];    // u -> states
__device__ float g_h[B_ * D_];            // input-proj pre-norm
__device__ float g_cat[B_ * KIN_];        // concat(stoch, a_norm)
__device__ float g_scales[M_BIG];         // per-row rms scales

// ---------------- helpers -------------------------------------------------
__device__ __forceinline__ unsigned f2tf32(float x) {
    unsigned r;
    asm("cvt.rna.tf32.f32 %0, %1;" : "=r"(r) : "f"(x));
    return r;
}

__device__ __forceinline__ void mma_tf32(float* c, const unsigned* a, const unsigned* b) {
    asm volatile(
        "mma.sync.aligned.m16n8k8.row.col.f32.tf32.tf32.f32 "
        "{%0,%1,%2,%3}, {%4,%5,%6,%7}, {%8,%9}, {%0,%1,%2,%3};"
        : "+f"(c[0]), "+f"(c[1]), "+f"(c[2]), "+f"(c[3])
        : "r"(a[0]), "r"(a[1]), "r"(a[2]), "r"(a[3]), "r"(b[0]), "r"(b[1]));
}

// ---------------- shift: tokens[b, 0..14, :] = deter[b, 1..15, :] --------
__global__ void shift_kernel(const float* __restrict__ deter, float* __restrict__ tokens)
{
    int idx = blockIdx.x * blockDim.x + threadIdx.x;     // over B*960 float4
    if (idx >= B_ * 960) return;
    int b = idx / 960;
    int r = idx - b * 960;
    const float4* s = reinterpret_cast<const float4*>(deter) + (size_t)b * 1024 + 64 + r;
    float4* d = reinterpret_cast<float4*>(tokens) + (size_t)b * 1024 + r;
    *d = *s;
}

// ---------------- concat(stoch, action/max(|action|,1)) ------------------
__global__ void concat_kernel(const float* __restrict__ stoch,
                              const float* __restrict__ action,
                              float* __restrict__ cat)
{
    int idx = blockIdx.x * blockDim.x + threadIdx.x;     // over B*1056
    if (idx >= B_ * KIN_) return;
    int b = idx / KIN_;
    int k = idx - b * KIN_;
    float v;
    if (k < STOCH_) {
        v = stoch[(size_t)b * STOCH_ + k];
    } else {
        float a = action[(size_t)b * ACT_ + (k - STOCH_)];
        v = a / fmaxf(fabsf(a), 1.0f);
    }
    cat[idx] = v;
}

// ---------------- per-row rms scale: scales[m] = rsqrt(mean(row^2)+eps) ---
__global__ void scale_kernel(const float* __restrict__ in, float* __restrict__ scales)
{
    int gwarp = (blockIdx.x * blockDim.x + threadIdx.x) >> 5;
    int lane  = threadIdx.x & 31;
    const float* rp = in + (size_t)gwarp * 256 + lane * 8;
    float v[8];
    *reinterpret_cast<float4*>(&v[0]) = *reinterpret_cast<const float4*>(rp);
    *reinterpret_cast<float4*>(&v[4]) = *reinterpret_cast<const float4*>(rp + 4);
    float s = 0.0f;
#pragma unroll
    for (int j = 0; j < 8; j++) s += v[j] * v[j];
#pragma unroll
    for (int o = 16; o > 0; o >>= 1) s += __shfl_xor_sync(0xffffffffu, s, o);
    if (lane == 0) scales[gwarp] = rsqrtf(s * (1.0f / 256.0f) + EPS_);
}

// ---------------- warp-per-row RMSNorm (rows of 256), optional SiLU -------
__global__ void rmsnorm_rows(const float* __restrict__ in, const float* __restrict__ w,
                             float* __restrict__ out, int out_stride, int do_silu)
{
    int gwarp = (blockIdx.x * blockDim.x + threadIdx.x) >> 5;
    int lane  = threadIdx.x & 31;
    const float* rp = in + (size_t)gwarp * 256 + lane * 8;
    float v[8];
    *reinterpret_cast<float4*>(&v[0]) = *reinterpret_cast<const float4*>(rp);
    *reinterpret_cast<float4*>(&v[4]) = *reinterpret_cast<const float4*>(rp + 4);
    float s = 0.0f;
#pragma unroll
    for (int j = 0; j < 8; j++) s += v[j] * v[j];
#pragma unroll
    for (int o = 16; o > 0; o >>= 1) s += __shfl_xor_sync(0xffffffffu, s, o);
    float scale = rsqrtf(s * (1.0f / 256.0f) + EPS_);

    float wl[8];
    *reinterpret_cast<float4*>(&wl[0]) = *reinterpret_cast<const float4*>(w + lane * 8);
    *reinterpret_cast<float4*>(&wl[4]) = *reinterpret_cast<const float4*>(w + lane * 8 + 4);

    float o8[8];
#pragma unroll
    for (int j = 0; j < 8; j++) {
        float y = v[j] * scale * wl[j];
        if (do_silu) y = y / (1.0f + expf(-y));
        o8[j] = y;
    }
    float* op = out + (size_t)gwarp * out_stride + lane * 8;
    *reinterpret_cast<float4*>(op)     = *reinterpret_cast<float4*>(&o8[0]);
    *reinterpret_cast<float4*>(op + 4) = *reinterpret_cast<float4*>(&o8[4]);
}

// ---------------- tf32 MMA mainloop (BM=64, BN=256) -----------------------
// A: [M, K] row-major (optionally normalized: a*scale[m]*nw[k]),
// W: [256, K] row-major (acts as B col-major [K, 256]).
// 8 warps: wm in {0,1} (32 rows each), wn in {0..3} (64 cols each).
__device__ __forceinline__ void mma_mainloop(
    const float* __restrict__ A, const float* __restrict__ W, int K,
    const float* __restrict__ scale, const float* __restrict__ nw,
    int m0, float acc[2][8][4],
    unsigned (*As)[65], unsigned (*Bs)[33])
{
    const int tid  = threadIdx.x;
    const int lane = tid & 31;
    const int wid  = tid >> 5;
    const int wm   = wid & 1;
    const int wn   = wid >> 1;
    const int gid  = lane >> 2;
    const int tig  = lane & 3;

    const int am = tid >> 2;             // 0..63
    const int ak = (tid & 3) * 8;        // 0,8,16,24
    const float sm = scale ? scale[m0 + am] : 1.0f;

    for (int k0 = 0; k0 < K; k0 += 32) {
        // ---- stage A tile (64 x 32), normalize inline, store tf32 [k][m]
        {
            const float* p = A + (size_t)(m0 + am) * K + k0 + ak;
            float4 v0 = *reinterpret_cast<const float4*>(p);
            float4 v1 = *reinterpret_cast<const float4*>(p + 4);
            float vv[8] = {v0.x, v0.y, v0.z, v0.w, v1.x, v1.y, v1.z, v1.w};
#pragma unroll
            for (int i = 0; i < 8; i++) {
                float f = vv[i] * sm;
                if (nw) f *= nw[k0 + ak + i];
                As[ak + i][am] = f2tf32(f);
            }
        }
        // ---- stage B tile (256 x 32), store tf32 [n][k]
        {
#pragma unroll
            for (int rr = 0; rr < 2; rr++) {
                int n  = (tid >> 1) + rr * 128;
                int kq = (tid & 1) * 16;
                const float* p = W + (size_t)n * K + k0 + kq;
#pragma unroll
                for (int q = 0; q < 4; q++) {
                    float4 v = *reinterpret_cast<const float4*>(p + q * 4);
                    Bs[n][kq + q * 4 + 0] = f2tf32(v.x);
                    Bs[n][kq + q * 4 + 1] = f2tf32(v.y);
                    Bs[n][kq + q * 4 + 2] = f2tf32(v.z);
                    Bs[n][kq + q * 4 + 3] = f2tf32(v.w);
                }
            }
        }
        __syncthreads();
        // ---- compute 4 k-steps of 8
#pragma unroll
        for (int ks = 0; ks < 4; ks++) {
            const int kb = ks * 8;
            unsigned a[2][4];
#pragma unroll
            for (int mt = 0; mt < 2; mt++) {
                int mrow = wm * 32 + mt * 16 + gid;
                a[mt][0] = As[kb + tig][mrow];
                a[mt][1] = As[kb + tig][mrow + 8];
                a[mt][2] = As[kb + tig + 4][mrow];
                a[mt][3] = As[kb + tig + 4][mrow + 8];
            }
#pragma unroll
            for (int j = 0; j < 8; j++) {
                int nb = wn * 64 + j * 8 + gid;
                unsigned b[2] = { Bs[nb][kb + tig], Bs[nb][kb + tig + 4] };
                mma_tf32(acc[0][j], a[0], b);
                mma_tf32(acc[1][j], a[1], b);
            }
        }
        __syncthreads();
    }
}

// ---------------- generic GEMM: C = A1@W1^T (+A2@W2^T) + b1 (+b2) (+Cin) --
__global__ __launch_bounds__(256, 2) void mma_gemm(
    const float* __restrict__ A1, const float* __restrict__ W1, int K1,
    const float* __restrict__ scale1, const float* __restrict__ nw1,
    const float* __restrict__ A2, const float* __restrict__ W2, int K2,
    const float* __restrict__ scale2, const float* __restrict__ nw2,
    const float* __restrict__ bias1, const float* __restrict__ bias2,
    const float* __restrict__ Cin, float* __restrict__ C)
{
    extern __shared__ unsigned smem_u[];
    unsigned (*As)[65] = reinterpret_cast<unsigned(*)[65]>(smem_u);
    unsigned (*Bs)[33] = reinterpret_cast<unsigned(*)[33]>(smem_u + 32 * 65);

    const int m0 = blockIdx.x * 64;
    float acc[2][8][4];
#pragma unroll
    for (int mt = 0; mt < 2; mt++)
#pragma unroll
        for (int j = 0; j < 8; j++)
#pragma unroll
            for (int q = 0; q < 4; q++) acc[mt][j][q] = 0.0f;

    mma_mainloop(A1, W1, K1, scale1, nw1, m0, acc, As, Bs);
    if (A2) mma_mainloop(A2, W2, K2, scale2, nw2, m0, acc, As, Bs);

    const int lane = threadIdx.x & 31;
    const int wid  = threadIdx.x >> 5;
    const int wm   = wid & 1, wn = wid >> 1;
    const int gid  = lane >> 2, tig = lane & 3;

#pragma unroll
    for (int j = 0; j < 8; j++) {
        int col = wn * 64 + j * 8 + tig * 2;
        float b0 = bias1[col]     + (bias2 ? bias2[col]     : 0.0f);
        float b1 = bias1[col + 1] + (bias2 ? bias2[col + 1] : 0.0f);
#pragma unroll
        for (int mt = 0; mt < 2; mt++) {
            int row = m0 + wm * 32 + mt * 16 + gid;
            size_t i0 = (size_t)row * 256 + col;
            size_t i1 = (size_t)(row + 8) * 256 + col;
            float2 o0, o1;
            o0.x = acc[mt][j][0] + b0; o0.y = acc[mt][j][1] + b1;
            o1.x = acc[mt][j][2] + b0; o1.y = acc[mt][j][3] + b1;
            if (Cin) {
                float2 c0 = *reinterpret_cast<const float2*>(Cin + i0);
                float2 c1 = *reinterpret_cast<const float2*>(Cin + i1);
                o0.x += c0.x; o0.y += c0.y;
                o1.x += c1.x; o1.y += c1.y;
            }
            *reinterpret_cast<float2*>(C + i0) = o0;
            *reinterpret_cast<float2*>(C + i1) = o1;
        }
    }
}

// ---------------- GEMM1 + fused scan: states = scan(x@Wi^T + bi) ----------
// BM=64 rows = 4 full batches (16 tokens each); BN=256 = full S.
__global__ __launch_bounds__(256, 2) void mma_gemm_scan(
    const float* __restrict__ A, const float* __restrict__ W,
    const float* __restrict__ scale, const float* __restrict__ nw,
    const float* __restrict__ bias, const float* __restrict__ log_decay,
    float* __restrict__ states)
{
    extern __shared__ unsigned smem_u[];
    unsigned (*As)[65] = reinterpret_cast<unsigned(*)[65]>(smem_u);
    unsigned (*Bs)[33] = reinterpret_cast<unsigned(*)[33]>(smem_u + 32 * 65);
    float (*Us)[260]   = reinterpret_cast<float(*)[260]>(smem_u);

    const int m0 = blockIdx.x * 64;
    float acc[2][8][4];
#pragma unroll
    for (int mt = 0; mt < 2; mt++)
#pragma unroll
        for (int j = 0; j < 8; j++)
#pragma unroll
            for (int q = 0; q < 4; q++) acc[mt][j][q] = 0.0f;

    mma_mainloop(A, W, 256, scale, nw, m0, acc, As, Bs);

    const int tid  = threadIdx.x;
    const int lane = tid & 31;
    const int wid  = tid >> 5;
    const int wm   = wid & 1, wn = wid >> 1;
    const int gid  = lane >> 2, tig = lane & 3;

    // u tile (+bias) into smem
#pragma unroll
    for (int j = 0; j < 8; j++) {
        int col = wn * 64 + j * 8 + tig * 2;
        float b0 = bias[col], b1 = bias[col + 1];
#pragma unroll
        for (int mt = 0; mt < 2; mt++) {
            int r = wm * 32 + mt * 16 + gid;
            Us[r][col]         = acc[mt][j][0] + b0;
            Us[r][col + 1]     = acc[mt][j][1] + b1;
            Us[r + 8][col]     = acc[mt][j][2] + b0;
            Us[r + 8][col + 1] = acc[mt][j][3] + b1;
        }
    }
    __syncthreads();

    // scan along t within each of the 4 batches, per column
#pragma unroll
    for (int rep = 0; rep < 4; rep++) {
        int task = rep * 256 + tid;
        int bb = task >> 8;
        int c  = task & 255;
        float dec = 1.0f / (1.0f + expf(-log_decay[c]));
        float st = 0.0f;
#pragma unroll
        for (int t = 0; t < 16; t++) {
            st = dec * st + Us[bb * 16 + t][c];
            Us[bb * 16 + t][c] = st;
        }
    }
    __syncthreads();

    // coalesced store of states tile
#pragma unroll
    for (int i = 0; i < 16; i++) {
        int f  = i * 256 + tid;       // float4 index within tile
        int r  = f >> 6;
        int c4 = (f & 63) * 4;
        float4 v = *reinterpret_cast<float4*>(&Us[r][c4]);
        *reinterpret_cast<float4*>(states + (size_t)(m0 + r) * 256 + c4) = v;
    }
}

// ---------------- launch -------------------------------------------------
extern "C" void kernel_launch(void* const* d_in, const int* in_sizes, int n_in,
                              void* d_out, int out_size)
{
    const float* stoch      = (const float*)d_in[0];
    const float* deter      = (const float*)d_in[1];
    const float* action     = (const float*)d_in[2];
    const float* W0         = (const float*)d_in[3];
    const float* b0         = (const float*)d_in[4];
    const float* g0         = (const float*)d_in[5];
    const float* norm_w     = (const float*)d_in[6];
    const float* W_in       = (const float*)d_in[7];
    const float* b_in       = (const float*)d_in[8];
    const float* W_out      = (const float*)d_in[9];
    const float* b_out      = (const float*)d_in[10];
    const float* W_skip     = (const float*)d_in[11];
    const float* b_skip     = (const float*)d_in[12];
    const float* log_decay  = (const float*)d_in[13];
    const float* out_norm_w = (const float*)d_in[14];
    float* out = (float*)d_out;

    float *tokA, *tokB, *states, *h, *cat, *scales;
    cudaGetSymbolAddress((void**)&tokA,   g_tokA);
    cudaGetSymbolAddress((void**)&tokB,   g_tokB);
    cudaGetSymbolAddress((void**)&states, g_states);
    cudaGetSymbolAddress((void**)&h,      g_h);
    cudaGetSymbolAddress((void**)&cat,    g_cat);
    cudaGetSymbolAddress((void**)&scales, g_scales);

    const int SMEM_GEMM = (32 * 65 + 256 * 33) * 4;   // 42112
    const int SMEM_SCAN = 64 * 260 * 4;               // 66560
    cudaFuncSetAttribute(mma_gemm_scan,
                         cudaFuncAttributeMaxDynamicSharedMemorySize, SMEM_SCAN);

    // 1. token shift + 2. concat
    shift_kernel<<<(B_ * 960 + 255) / 256, 256>>>(deter, tokA);
    concat_kernel<<<(B_ * KIN_ + 255) / 256, 256>>>(stoch, action, cat);

    // 3. input proj: h = cat @ W0^T + b0  (M=4096, K=1056)
    mma_gemm<<<B_ / 64, 256, SMEM_GEMM>>>(
        cat, W0, KIN_, nullptr, nullptr,
        nullptr, nullptr, 0, nullptr, nullptr,
        b0, nullptr, nullptr, h);

    // 4. new_tok = silu(rmsnorm(h, g0)) -> tokens slot 15
    rmsnorm_rows<<<B_ / 8, 256>>>(h, g0, tokA + 15 * D_, T_ * D_, 1);

    // 5. S4 layers (ping-pong token buffers)
    float* P = tokA;
    float* Q = tokB;
    for (int l = 0; l < L_; l++) {
        const float* nw  = norm_w    + (size_t)l * D_;
        const float* Wi  = W_in      + (size_t)l * S_ * D_;
        const float* bi  = b_in      + (size_t)l * S_;
        const float* Wo  = W_out     + (size_t)l * D_ * S_;
        const float* bo  = b_out     + (size_t)l * D_;
        const float* Ws  = W_skip    + (size_t)l * D_ * D_;
        const float* bsk = b_skip    + (size_t)l * D_;
        const float* ld  = log_decay + (size_t)l * S_;

        // a. row scales of current tokens
        scale_kernel<<<M_BIG / 8, 256>>>(P, scales);

        // b. states = scan(rmsnorm(P)@Wi^T + bi)   [fused]
        mma_gemm_scan<<<M_BIG / 64, 256, SMEM_SCAN>>>(
            P, Wi, scales, nw, bi, ld, states);

        // c. Q = states@Wo^T + bo + rmsnorm(P)@Ws^T + bsk + P
        mma_gemm<<<M_BIG / 64, 256, SMEM_GEMM>>>(
            states, Wo, S_, nullptr, nullptr,
            P, Ws, D_, scales, nw,
            bo, bsk, P, Q);

        float* tmp = P; P = Q; Q = tmp;
    }

    // 6. final rmsnorm -> output (P holds final tokens)
    rmsnorm_rows<<<M_BIG / 8, 256>>>(P, out_norm_w, out, D_, 0);
}

// round 5
// speedup vs baseline: 1.5136x; 1.5136x over previous
#include <cuda_runtime.h>
#include <math.h>
#include <stdint.h>

#define B_    4096
#define T_    16
#define D_    256
#define L_    4
#define KIN_  1056
#define EPS_  1e-4f
#define M_BIG (B_ * T_)          // 65536

// ---------------- scratch ----------------
__device__ float g_tokA[M_BIG * D_];
__device__ float g_tokB[M_BIG * D_];
__device__ float g_states[M_BIG * D_];
__device__ float g_cat[B_ * KIN_];
__device__ float g_scales[M_BIG];
__device__ float g_Wi[L_ * D_ * D_];     // rna(W_in  * nw)
__device__ float g_Wo[L_ * D_ * D_];     // rna(W_out)
__device__ float g_Ws[L_ * D_ * D_];     // rna(W_skip * nw)
__device__ float g_W0r[D_ * KIN_];       // rna(W0)

// ---------------- PTX helpers ----------------
__device__ __forceinline__ uint32_t smem_u32(const void* p) {
    uint32_t a;
    asm("{ .reg .u64 t; cvta.to.shared.u64 t, %1; cvt.u32.u64 %0, t; }" : "=r"(a) : "l"(p));
    return a;
}
__device__ __forceinline__ uint32_t f2tf32(float x) {
    uint32_t r; asm("cvt.rna.tf32.f32 %0, %1;" : "=r"(r) : "f"(x)); return r;
}
__device__ __forceinline__ float rna(float x) { return __uint_as_float(f2tf32(x)); }

__device__ __forceinline__ void mma_tf32(float* c, const uint32_t* a, const uint32_t* b) {
    asm volatile(
        "mma.sync.aligned.m16n8k8.row.col.f32.tf32.tf32.f32 "
        "{%0,%1,%2,%3}, {%4,%5,%6,%7}, {%8,%9}, {%0,%1,%2,%3};"
        : "+f"(c[0]), "+f"(c[1]), "+f"(c[2]), "+f"(c[3])
        : "r"(a[0]), "r"(a[1]), "r"(a[2]), "r"(a[3]), "r"(b[0]), "r"(b[1]));
}
__device__ __forceinline__ void ldsm4(uint32_t* r, uint32_t addr) {
    asm volatile("ldmatrix.sync.aligned.m8n8.x4.shared.b16 {%0,%1,%2,%3}, [%4];"
                 : "=r"(r[0]), "=r"(r[1]), "=r"(r[2]), "=r"(r[3]) : "r"(addr));
}
__device__ __forceinline__ void cp16(uint32_t s, const float* g) {
    asm volatile("{ .reg .u64 gp; cvta.to.global.u64 gp, %1;\n\t"
                 "cp.async.cg.shared.global [%0], [gp], 16; }"
                 :: "r"(s), "l"(g) : "memory");
}
__device__ __forceinline__ void cp_commit() {
    asm volatile("cp.async.commit_group;" ::: "memory");
}
__device__ __forceinline__ void cp_wait1() {
    asm volatile("cp.async.wait_group 1;" ::: "memory");
}
__device__ __forceinline__ void cp_wait0() {
    asm volatile("cp.async.wait_group 0;" ::: "memory");
}

// ---------------- smem geometry (bytes) ----------------
// A stage: 64 rows x 144B  = 9216  (x2)
// B stage: 256 rows x 144B = 36864 (x2)
#define SM_A0   0
#define SM_A1   9216
#define SM_B0   18432
#define SM_B1   55296
#define SM_TOT  92160

struct GP { const float* A; int lda; const float* W; };

// stage one 32-k chunk: A manual (cvt.rna), B via cp.async
__device__ __forceinline__ void stage_chunk(float* smf, uint32_t sm32, int buf,
                                            const GP& g, int k0)
{
    const int tid = threadIdx.x;
    // A: 64 x 32
    {
        int row = tid >> 2, kc = (tid & 3) * 8;
        const float* p = g.A + (size_t)row * g.lda + k0 + kc;
        float4 v0 = *(const float4*)p;
        float4 v1 = *(const float4*)(p + 4);
        uint4 u0 = { f2tf32(v0.x), f2tf32(v0.y), f2tf32(v0.z), f2tf32(v0.w) };
        uint4 u1 = { f2tf32(v1.x), f2tf32(v1.y), f2tf32(v1.z), f2tf32(v1.w) };
        char* d = (char*)smf + (buf ? SM_A1 : SM_A0) + row * 144 + kc * 4;
        *(uint4*)d = u0;
        *(uint4*)(d + 16) = u1;
    }
    // B: 256 x 32 via cp.async
    {
        const float* p = g.W + (size_t)tid * g.lda + k0;
        uint32_t d = sm32 + (buf ? SM_B1 : SM_B0) + tid * 144;
#pragma unroll
        for (int j = 0; j < 8; j++) cp16(d + j * 16, p + j * 4);
    }
}

// main pipelined GEMM: acc += A0@W0^T (chunks nc0), then optional mid-scale,
// then acc += A1@W1^T (chunks nc1). BM=64, BN=256, 8 warps (2m x 4n).
__device__ __forceinline__ void gemm_main(
    float* smf, uint32_t sm32,
    const GP& g0, int nc0, const GP& g1, int nc1,
    const float* midscale, int m0, float acc[2][8][4])
{
    const int tid  = threadIdx.x;
    const int lane = tid & 31, wid = tid >> 5;
    const int wm = wid & 1, wn = wid >> 1;
    const int gid = lane >> 2;
    const int lr = lane & 7, lb8 = (lane >> 3) & 1, lb16 = (lane >> 4) & 1;

    const uint32_t aoff0 = (uint32_t)(wm * 32 + lr + lb8 * 8) * 144 + lb16 * 16;
    const uint32_t aoff1 = aoff0 + 16 * 144;
    const uint32_t boff  = (uint32_t)(wn * 64 + lr + lb16 * 8) * 144 + lb8 * 16;

    const int NC = nc0 + nc1;
    stage_chunk(smf, sm32, 0, g0, 0);
    cp_commit();

    for (int i = 0; i < NC; i++) {
        const int b = i & 1;
        if (i + 1 < NC) {
            const GP& gn = (i + 1 < nc0) ? g0 : g1;
            int k0n = ((i + 1 < nc0) ? i + 1 : i + 1 - nc0) * 32;
            stage_chunk(smf, sm32, (i + 1) & 1, gn, k0n);
            cp_commit();
            cp_wait1();
        } else {
            cp_wait0();
        }
        __syncthreads();

        if (midscale && i == nc0) {
            float s[2][2];
#pragma unroll
            for (int mt = 0; mt < 2; mt++) {
                int r = m0 + wm * 32 + mt * 16 + gid;
                s[mt][0] = midscale[r];
                s[mt][1] = midscale[r + 8];
            }
#pragma unroll
            for (int mt = 0; mt < 2; mt++)
#pragma unroll
                for (int j = 0; j < 8; j++) {
                    acc[mt][j][0] *= s[mt][0]; acc[mt][j][1] *= s[mt][0];
                    acc[mt][j][2] *= s[mt][1]; acc[mt][j][3] *= s[mt][1];
                }
        }

        const uint32_t sA = sm32 + (b ? SM_A1 : SM_A0);
        const uint32_t sB = sm32 + (b ? SM_B1 : SM_B0);
#pragma unroll
        for (int ks = 0; ks < 4; ks++) {
            uint32_t a0[4], a1[4], bf[4][4];
            ldsm4(a0, sA + aoff0 + ks * 32);
            ldsm4(a1, sA + aoff1 + ks * 32);
#pragma unroll
            for (int pr = 0; pr < 4; pr++)
                ldsm4(bf[pr], sB + boff + pr * 2304 + ks * 32);
#pragma unroll
            for (int pr = 0; pr < 4; pr++) {
                mma_tf32(acc[0][2*pr],   a0, &bf[pr][0]);
                mma_tf32(acc[0][2*pr+1], a0, &bf[pr][2]);
                mma_tf32(acc[1][2*pr],   a1, &bf[pr][0]);
                mma_tf32(acc[1][2*pr+1], a1, &bf[pr][2]);
            }
        }
        __syncthreads();
    }
}

// =========== prologue kernels ===========
__global__ void prep_weights(const float* __restrict__ Wi, const float* __restrict__ Wo,
                             const float* __restrict__ Wsk, const float* __restrict__ nw,
                             const float* __restrict__ W0)
{
    int i = blockIdx.x * blockDim.x + threadIdx.x;
    if (i < L_ * D_ * D_) {
        int l = i >> 16, k = i & 255;
        float w = nw[l * D_ + k];
        g_Wi[i] = rna(Wi[i] * w);
        g_Ws[i] = rna(Wsk[i] * w);
        g_Wo[i] = rna(Wo[i]);
    }
    if (i < D_ * KIN_) g_W0r[i] = rna(W0[i]);
}

__global__ void shift_scale_kernel(const float* __restrict__ deter,
                                   float* __restrict__ tok, float* __restrict__ scales)
{
    int gw = (blockIdx.x * blockDim.x + threadIdx.x) >> 5;
    if (gw >= B_ * 15) return;
    int lane = threadIdx.x & 31;
    int b = gw / 15, t = gw - b * 15;
    const float4* src = (const float4*)(deter + (size_t)b * 4096 + (t + 1) * 256) + lane;
    float4* dst = (float4*)(tok + (size_t)b * 4096 + t * 256) + lane;
    float4 v0 = src[0], v1 = src[32];
    dst[0] = v0; dst[32] = v1;
    float s = v0.x*v0.x + v0.y*v0.y + v0.z*v0.z + v0.w*v0.w
            + v1.x*v1.x + v1.y*v1.y + v1.z*v1.z + v1.w*v1.w;
#pragma unroll
    for (int o = 16; o > 0; o >>= 1) s += __shfl_xor_sync(0xffffffffu, s, o);
    if (lane == 0) scales[b * 16 + t] = rsqrtf(s * (1.0f / 256.0f) + EPS_);
}

__global__ void concat_kernel(const float* __restrict__ stoch,
                              const float* __restrict__ action,
                              float* __restrict__ cat)
{
    int idx = blockIdx.x * blockDim.x + threadIdx.x;
    if (idx >= B_ * KIN_) return;
    int b = idx / KIN_;
    int k = idx - b * KIN_;
    float v;
    if (k < 1024) v = stoch[(size_t)b * 1024 + k];
    else {
        float a = action[(size_t)b * 32 + (k - 1024)];
        v = a / fmaxf(fabsf(a), 1.0f);
    }
    cat[idx] = v;
}

// acc -> Us[64][260] with optional per-element transform done by caller afterwards
__device__ __forceinline__ void acc_to_us(float* Us, float acc[2][8][4],
                                          const float* b1, const float* b2,
                                          const float* rowscale, int m0)
{
    const int lane = threadIdx.x & 31, wid = threadIdx.x >> 5;
    const int wm = wid & 1, wn = wid >> 1;
    const int gid = lane >> 2, tig = lane & 3;
#pragma unroll
    for (int mt = 0; mt < 2; mt++) {
        int r0 = wm * 32 + mt * 16 + gid;
        float s0 = rowscale ? rowscale[m0 + r0] : 1.0f;
        float s1 = rowscale ? rowscale[m0 + r0 + 8] : 1.0f;
#pragma unroll
        for (int j = 0; j < 8; j++) {
            int col = wn * 64 + j * 8 + tig * 2;
            float bb0 = (b1 ? b1[col]   : 0.f) + (b2 ? b2[col]   : 0.f);
            float bb1 = (b1 ? b1[col+1] : 0.f) + (b2 ? b2[col+1] : 0.f);
            Us[r0 * 260 + col]           = acc[mt][j][0] * s0 + bb0;
            Us[r0 * 260 + col + 1]       = acc[mt][j][1] * s0 + bb1;
            Us[(r0 + 8) * 260 + col]     = acc[mt][j][2] * s1 + bb0;
            Us[(r0 + 8) * 260 + col + 1] = acc[mt][j][3] * s1 + bb1;
        }
    }
}

// =========== input proj + rmsnorm + silu ===========
__global__ __launch_bounds__(256, 2)
void k_proj(const float* __restrict__ cat, const float* __restrict__ b0,
            const float* __restrict__ g0, float* __restrict__ tokA,
            float* __restrict__ scales)
{
    extern __shared__ float smf[];
    uint32_t sm32 = smem_u32(smf);
    const int tid = threadIdx.x, wid = tid >> 5, lane = tid & 31;
    const int m0 = blockIdx.x * 64;

    float acc[2][8][4];
#pragma unroll
    for (int mt = 0; mt < 2; mt++)
#pragma unroll
        for (int j = 0; j < 8; j++)
#pragma unroll
            for (int q = 0; q < 4; q++) acc[mt][j][q] = 0.f;

    GP g = { cat + (size_t)m0 * KIN_, KIN_, g_W0r };
    gemm_main(smf, sm32, g, 33, g, 0, nullptr, m0, acc);

    float* Us = smf;
    acc_to_us(Us, acc, nullptr, nullptr, nullptr, m0);
    __syncthreads();

#pragma unroll
    for (int k = 0; k < 8; k++) {
        int row = k * 8 + wid;
        int m = m0 + row;               // batch index
        float v[8]; float sum = 0.f;
#pragma unroll
        for (int j = 0; j < 8; j++) {
            int c = lane + 32 * j;
            v[j] = Us[row * 260 + c] + b0[c];
            sum += v[j] * v[j];
        }
#pragma unroll
        for (int o = 16; o > 0; o >>= 1) sum += __shfl_xor_sync(0xffffffffu, sum, o);
        float sc = rsqrtf(sum * (1.0f / 256.0f) + EPS_);
        float s2 = 0.f;
#pragma unroll
        for (int j = 0; j < 8; j++) {
            int c = lane + 32 * j;
            float y = v[j] * sc * g0[c];
            y = y / (1.0f + expf(-y));
            s2 += y * y;
            tokA[(size_t)m * 4096 + 3840 + c] = y;
        }
#pragma unroll
        for (int o = 16; o > 0; o >>= 1) s2 += __shfl_xor_sync(0xffffffffu, s2, o);
        if (lane == 0) scales[m * 16 + 15] = rsqrtf(s2 * (1.0f / 256.0f) + EPS_);
    }
}

// =========== GEMM1 + fused scan ===========
__global__ __launch_bounds__(256, 2)
void k_gemm_scan(const float* __restrict__ P, const float* __restrict__ Wi,
                 const float* __restrict__ bi, const float* __restrict__ ldc,
                 const float* __restrict__ scales, float* __restrict__ states)
{
    extern __shared__ float smf[];
    uint32_t sm32 = smem_u32(smf);
    const int tid = threadIdx.x;
    const int m0 = blockIdx.x * 64;

    float acc[2][8][4];
#pragma unroll
    for (int mt = 0; mt < 2; mt++)
#pragma unroll
        for (int j = 0; j < 8; j++)
#pragma unroll
            for (int q = 0; q < 4; q++) acc[mt][j][q] = 0.f;

    GP g = { P + (size_t)m0 * 256, 256, Wi };
    gemm_main(smf, sm32, g, 8, g, 0, nullptr, m0, acc);

    float* Us = smf;
    acc_to_us(Us, acc, bi, nullptr, scales, m0);   // u = scale_m*acc + bi
    __syncthreads();

    // scan along t (4 batches x 256 cols)
#pragma unroll
    for (int rep = 0; rep < 4; rep++) {
        int task = rep * 256 + tid;
        int bb = task >> 8;
        int c  = task & 255;
        float dec = 1.0f / (1.0f + expf(-ldc[c]));
        float st = 0.0f;
#pragma unroll
        for (int t = 0; t < 16; t++) {
            st = dec * st + Us[(bb * 16 + t) * 260 + c];
            Us[(bb * 16 + t) * 260 + c] = st;
        }
    }
    __syncthreads();
#pragma unroll
    for (int it = 0; it < 16; it++) {
        int f = it * 256 + tid;
        int row = f >> 6;
        int c4 = (f & 63) * 4;
        float4 v = *(float4*)&Us[row * 260 + c4];
        *(float4*)&states[(size_t)(m0 + row) * 256 + c4] = v;
    }
}

// =========== GEMM2: Q = scale*(P@Ws'^T) + states@Wo^T + bo + bsk + P ===========
__global__ __launch_bounds__(256, 2)
void k_gemm2(const float* __restrict__ P, const float* __restrict__ Wsp,
             const float* __restrict__ states, const float* __restrict__ Wo,
             const float* __restrict__ scales_in,
             const float* __restrict__ bo, const float* __restrict__ bsk,
             float* __restrict__ Q, float* __restrict__ scales_out,
             const float* __restrict__ onw, int last)
{
    extern __shared__ float smf[];
    uint32_t sm32 = smem_u32(smf);
    const int tid = threadIdx.x, wid = tid >> 5, lane = tid & 31;
    const int m0 = blockIdx.x * 64;

    float acc[2][8][4];
#pragma unroll
    for (int mt = 0; mt < 2; mt++)
#pragma unroll
        for (int j = 0; j < 8; j++)
#pragma unroll
            for (int q = 0; q < 4; q++) acc[mt][j][q] = 0.f;

    GP gA = { P + (size_t)m0 * 256,      256, Wsp };
    GP gB = { states + (size_t)m0 * 256, 256, Wo  };
    gemm_main(smf, sm32, gA, 8, gB, 8, scales_in, m0, acc);

    float* Us = smf;
    acc_to_us(Us, acc, bo, bsk, nullptr, m0);
    __syncthreads();

    const float* Pres = P + (size_t)m0 * 256;
#pragma unroll
    for (int k = 0; k < 8; k++) {
        int row = k * 8 + wid;
        int m = m0 + row;
        float v[8]; float sum = 0.f;
#pragma unroll
        for (int j = 0; j < 8; j++) {
            int c = lane + 32 * j;
            v[j] = Us[row * 260 + c] + Pres[(size_t)row * 256 + c];
            sum += v[j] * v[j];
        }
#pragma unroll
        for (int o = 16; o > 0; o >>= 1) sum += __shfl_xor_sync(0xffffffffu, sum, o);
        float sc = rsqrtf(sum * (1.0f / 256.0f) + EPS_);
        if (last) {
#pragma unroll
            for (int j = 0; j < 8; j++) {
                int c = lane + 32 * j;
                Q[(size_t)m * 256 + c] = v[j] * sc * onw[c];
            }
        } else {
#pragma unroll
            for (int j = 0; j < 8; j++)
                Q[(size_t)m * 256 + lane + 32 * j] = v[j];
            if (lane == 0) scales_out[m] = sc;
        }
    }
}

// ---------------- launch ----------------
extern "C" void kernel_launch(void* const* d_in, const int* in_sizes, int n_in,
                              void* d_out, int out_size)
{
    const float* stoch      = (const float*)d_in[0];
    const float* deter      = (const float*)d_in[1];
    const float* action     = (const float*)d_in[2];
    const float* W0         = (const float*)d_in[3];
    const float* b0         = (const float*)d_in[4];
    const float* g0         = (const float*)d_in[5];
    const float* norm_w     = (const float*)d_in[6];
    const float* W_in       = (const float*)d_in[7];
    const float* b_in       = (const float*)d_in[8];
    const float* W_out      = (const float*)d_in[9];
    const float* b_out      = (const float*)d_in[10];
    const float* W_skip     = (const float*)d_in[11];
    const float* b_skip     = (const float*)d_in[12];
    const float* log_decay  = (const float*)d_in[13];
    const float* out_norm_w = (const float*)d_in[14];
    float* out = (float*)d_out;

    float *tokA, *tokB, *states, *cat, *scales, *Wi_s, *Wo_s, *Ws_s, *W0r;
    cudaGetSymbolAddress((void**)&tokA,   g_tokA);
    cudaGetSymbolAddress((void**)&tokB,   g_tokB);
    cudaGetSymbolAddress((void**)&states, g_states);
    cudaGetSymbolAddress((void**)&cat,    g_cat);
    cudaGetSymbolAddress((void**)&scales, g_scales);
    cudaGetSymbolAddress((void**)&Wi_s,   g_Wi);
    cudaGetSymbolAddress((void**)&Wo_s,   g_Wo);
    cudaGetSymbolAddress((void**)&Ws_s,   g_Ws);
    cudaGetSymbolAddress((void**)&W0r,    g_W0r);

    cudaFuncSetAttribute(k_proj,      cudaFuncAttributeMaxDynamicSharedMemorySize, SM_TOT);
    cudaFuncSetAttribute(k_gemm_scan, cudaFuncAttributeMaxDynamicSharedMemorySize, SM_TOT);
    cudaFuncSetAttribute(k_gemm2,     cudaFuncAttributeMaxDynamicSharedMemorySize, SM_TOT);

    prep_weights<<<(D_ * KIN_ + 255) / 256 + 1, 256>>>(W_in, W_out, W_skip, norm_w, W0);
    shift_scale_kernel<<<B_ * 15 / 8, 256>>>(deter, tokA, scales);
    concat_kernel<<<(B_ * KIN_ + 255) / 256, 256>>>(stoch, action, cat);
    k_proj<<<B_ / 64, 256, SM_TOT>>>(cat, b0, g0, tokA, scales);

    float* Pb = tokA;
    float* Qb = tokB;
    for (int l = 0; l < L_; l++) {
        const float* Wi  = Wi_s + (size_t)l * D_ * D_;
        const float* Wo  = Wo_s + (size_t)l * D_ * D_;
        const float* Ws  = Ws_s + (size_t)l * D_ * D_;
        const float* bi  = b_in      + (size_t)l * D_;
        const float* bo  = b_out     + (size_t)l * D_;
        const float* bsk = b_skip    + (size_t)l * D_;
        const float* ld  = log_decay + (size_t)l * D_;

        k_gemm_scan<<<M_BIG / 64, 256, SM_TOT>>>(Pb, Wi, bi, ld, scales, states);

        int last = (l == L_ - 1);
        k_gemm2<<<M_BIG / 64, 256, SM_TOT>>>(
            Pb, Ws, states, Wo, scales, bo, bsk,
            last ? out : Qb, scales, out_norm_w, last);

        float* tmp = Pb; Pb = Qb; Qb = tmp;
    }
}